// round 1
// baseline (speedup 1.0000x reference)
#include <cuda_runtime.h>
#include <math.h>

#define D 64
#define EPS_M 1e-7f

__global__ void __launch_bounds__(D) genconv_kernel(
    const float* __restrict__ nf,     // [N, 64]
    const float* __restrict__ ef,     // [E, 64]
    const float* __restrict__ W,      // [64, 64]
    const float* __restrict__ bvec,   // [64]
    const float* __restrict__ scale,  // [1]
    const int*   __restrict__ src,    // [E]
    const int*   __restrict__ dst,    // [E] sorted
    float*       __restrict__ out,    // [N, 64]
    int n_nodes, int n_edges)
{
    const int n = blockIdx.x;
    const int t = threadIdx.x;  // channel 0..63

    // Binary search the contiguous edge range [s, e_end) with dst == n.
    // All threads compute it redundantly (same addresses -> broadcast loads).
    int lo = 0, hi = n_edges;
    while (lo < hi) { int mid = (lo + hi) >> 1; if (dst[mid] <  n) lo = mid + 1; else hi = mid; }
    const int s = lo;
    hi = n_edges;
    while (lo < hi) { int mid = (lo + hi) >> 1; if (dst[mid] <= n) lo = mid + 1; else hi = mid; }
    const int e_end = lo;

    // Online softmax over this node's incoming edges, per channel t.
    // m = relu(h[src] + ef) + eps ; agg = sum(m * exp(m - mx)) / sum(exp(m - mx))
    float mx = -3.0e38f, se = 0.f, sme = 0.f;
    for (int e = s; e < e_end; ++e) {
        const int sp = src[e];                 // broadcast across block
        const float m = fmaxf(nf[sp * D + t] + ef[e * D + t], 0.f) + EPS_M;
        const float newmx = fmaxf(mx, m);
        const float corr = __expf(mx - newmx); // 0 on first iter
        const float p    = __expf(m  - newmx);
        se  = fmaf(se,  corr, p);
        sme = fmaf(sme, corr, m * p);
        mx  = newmx;
    }
    const float agg = (se > 0.f) ? (sme / se) : 0.f;
    const float h   = nf[n * D + t];

    // Block-wide reductions: ||agg||^2 and ||h||^2 over 64 channels.
    float a2 = agg * agg;
    float h2 = h * h;
    #pragma unroll
    for (int o = 16; o > 0; o >>= 1) {
        a2 += __shfl_xor_sync(0xffffffffu, a2, o);
        h2 += __shfl_xor_sync(0xffffffffu, h2, o);
    }
    __shared__ float s_a2[2], s_h2[2];
    __shared__ float s_feat[D];
    const int w = t >> 5;
    if ((t & 31) == 0) { s_a2[w] = a2; s_h2[w] = h2; }
    __syncthreads();
    const float agg_n2 = s_a2[0] + s_a2[1];
    const float h_n2   = s_h2[0] + s_h2[1];

    // MessageNorm + residual
    const float inv_norm = 1.0f / fmaxf(sqrtf(agg_n2), 1e-12f);
    const float feat = fmaf(agg * inv_norm, sqrtf(h_n2) * scale[0], h);
    s_feat[t] = feat;
    __syncthreads();

    // Fused linear: out[n][t] = b[t] + sum_d feat[d] * W[t][d]
    float acc = bvec[t];
    const float* __restrict__ wrow = W + t * D;
    #pragma unroll 16
    for (int d = 0; d < D; ++d)
        acc = fmaf(s_feat[d], wrow[d], acc);
    out[n * D + t] = acc;
}

extern "C" void kernel_launch(void* const* d_in, const int* in_sizes, int n_in,
                              void* d_out, int out_size)
{
    const float* nf    = (const float*)d_in[0];
    const float* ef    = (const float*)d_in[1];
    const float* W     = (const float*)d_in[2];
    const float* bvec  = (const float*)d_in[3];
    const float* scale = (const float*)d_in[4];
    const int*   src   = (const int*)d_in[5];
    const int*   dst   = (const int*)d_in[6];
    float* out = (float*)d_out;

    const int n_nodes = in_sizes[0] / D;
    const int n_edges = in_sizes[5];

    genconv_kernel<<<n_nodes, D>>>(nf, ef, W, bvec, scale, src, dst,
                                   out, n_nodes, n_edges);
}

// round 2
// speedup vs baseline: 6.9093x; 6.9093x over previous
#include <cuda_runtime.h>
#include <math.h>

#define D 64
#define EPS_M 1e-7f
#define N_MAX 100001
#define NPB 4            // nodes per block

__device__ float g_WT[D * D];       // WT[d][t] = W[t][d]
__device__ int   g_off[N_MAX + 1];  // CSR offsets into sorted dst

// ---- pre-kernel 1: transpose W ----
__global__ void transpose_W(const float* __restrict__ W) {
    int i = blockIdx.x * blockDim.x + threadIdx.x;
    if (i < D * D) {
        int r = i >> 6, c = i & 63;       // W[r][c]
        g_WT[c * D + r] = W[i];
    }
}

// ---- pre-kernel 2: CSR offsets from sorted dst ----
__global__ void build_offsets(const int* __restrict__ dst, int n_nodes, int n_edges) {
    int n = blockIdx.x * blockDim.x + threadIdx.x;
    if (n > n_nodes) return;
    if (n == n_nodes) { g_off[n] = n_edges; return; }
    int lo = 0, hi = n_edges;             // lower_bound(dst, n)
    while (lo < hi) { int mid = (lo + hi) >> 1; if (dst[mid] < n) lo = mid + 1; else hi = mid; }
    g_off[n] = lo;
}

// ---- main fused kernel: 256 threads = 4 node-groups of 64 ----
__global__ void __launch_bounds__(256) genconv_kernel(
    const float* __restrict__ nf,     // [N, 64]
    const float* __restrict__ ef,     // [E, 64]
    const float* __restrict__ bvec,   // [64]
    const float* __restrict__ scale,  // [1]
    const int*   __restrict__ src,    // [E]
    float*       __restrict__ out,    // [N, 64]
    int n_nodes)
{
    __shared__ float sWT[D * D];          // 16 KB
    __shared__ float s_feat[NPB][D];
    __shared__ float s_red[NPB][2][2];    // [group][warp-in-group][{a2,h2}]

    const int g  = threadIdx.x >> 6;      // group 0..3
    const int tc = threadIdx.x & 63;      // channel
    const int node = blockIdx.x * NPB + g;
    const bool active = (node < n_nodes);

    // stage WT into smem (coalesced; used after barrier #2)
    for (int i = threadIdx.x; i < D * D; i += 256)
        sWT[i] = g_WT[i];

    int s = 0, e_end = 0;
    if (active) { s = g_off[node]; e_end = g_off[node + 1]; }

    // online per-channel softmax + weighted sum over this node's edge run
    float mx = -3.0e38f, se = 0.f, sme = 0.f;
    #pragma unroll 2
    for (int e = s; e < e_end; ++e) {
        const int sp = __ldg(&src[e]);    // broadcast within group
        const float m = fmaxf(nf[sp * D + tc] + ef[e * D + tc], 0.f) + EPS_M;
        const float newmx = fmaxf(mx, m);
        const float corr = __expf(mx - newmx);
        const float p    = __expf(m  - newmx);
        se  = fmaf(se,  corr, p);
        sme = fmaf(sme, corr, m * p);
        mx  = newmx;
    }
    const float agg = (se > 0.f) ? (sme / se) : 0.f;
    const float h   = active ? nf[node * D + tc] : 0.f;

    // group-wide (64-lane) reductions of ||agg||^2, ||h||^2
    float a2 = agg * agg, h2 = h * h;
    #pragma unroll
    for (int o = 16; o > 0; o >>= 1) {
        a2 += __shfl_xor_sync(0xffffffffu, a2, o);
        h2 += __shfl_xor_sync(0xffffffffu, h2, o);
    }
    const int w = tc >> 5;
    if ((tc & 31) == 0) { s_red[g][w][0] = a2; s_red[g][w][1] = h2; }
    __syncthreads();                                   // barrier #1
    const float agg_n2 = s_red[g][0][0] + s_red[g][1][0];
    const float h_n2   = s_red[g][0][1] + s_red[g][1][1];

    // MessageNorm + residual
    const float inv_norm = 1.0f / fmaxf(sqrtf(agg_n2), 1e-12f);
    const float feat = fmaf(agg * inv_norm, sqrtf(h_n2) * scale[0], h);
    s_feat[g][tc] = feat;
    __syncthreads();                                   // barrier #2 (covers sWT too)

    // fused linear: out[node][tc] = b[tc] + sum_d feat[d] * WT[d][tc]
    if (active) {
        float acc = bvec[tc];
        #pragma unroll 16
        for (int d = 0; d < D; ++d)
            acc = fmaf(s_feat[g][d], sWT[d * D + tc], acc);  // conflict-free + broadcast
        out[node * D + tc] = acc;
    }
}

extern "C" void kernel_launch(void* const* d_in, const int* in_sizes, int n_in,
                              void* d_out, int out_size)
{
    const float* nf    = (const float*)d_in[0];
    const float* ef    = (const float*)d_in[1];
    const float* W     = (const float*)d_in[2];
    const float* bvec  = (const float*)d_in[3];
    const float* scale = (const float*)d_in[4];
    const int*   src   = (const int*)d_in[5];
    const int*   dst   = (const int*)d_in[6];
    float* out = (float*)d_out;

    const int n_nodes = in_sizes[0] / D;
    const int n_edges = in_sizes[5];

    transpose_W<<<(D * D + 255) / 256, 256>>>(W);
    build_offsets<<<(n_nodes + 256) / 256, 256>>>(dst, n_nodes, n_edges);
    genconv_kernel<<<(n_nodes + NPB - 1) / NPB, 256>>>(nf, ef, bvec, scale, src,
                                                       out, n_nodes);
}

// round 3
// speedup vs baseline: 12.6683x; 1.8335x over previous
#include <cuda_runtime.h>
#include <math.h>

#define D 64
#define EPS_M 1e-7f
#define N_MAX 100001

__device__ float g_WT[D * D];       // g_WT[d*64 + c] = W[c][d]
__device__ int   g_off[N_MAX + 1];  // CSR offsets into sorted dst

// ---- single pre-kernel: CSR offsets + W transpose ----
__global__ void prep_kernel(const int* __restrict__ dst,
                            const float* __restrict__ W,
                            int n_nodes, int n_edges)
{
    const int i = blockIdx.x * blockDim.x + threadIdx.x;
    if (i < D * D) {                      // transpose W (one-time, tiny)
        int r = i >> 6, c = i & 63;       // W[r][c]
        g_WT[c * D + r] = W[i];
    }
    if (i <= n_nodes) {
        if (i == n_nodes) { g_off[i] = n_edges; }
        else {
            int lo = 0, hi = n_edges;     // lower_bound(dst, i)
            while (lo < hi) { int mid = (lo + hi) >> 1; if (dst[mid] < i) lo = mid + 1; else hi = mid; }
            g_off[i] = lo;
        }
    }
}

// ---- main kernel: one warp per node, grid-stride over nodes ----
__global__ void __launch_bounds__(256) genconv_kernel(
    const float* __restrict__ nf,     // [N, 64]
    const float* __restrict__ ef,     // [E, 64]
    const float* __restrict__ bvec,   // [64]
    const float* __restrict__ scale,  // [1]
    const int*   __restrict__ src,    // [E]
    float*       __restrict__ out,    // [N, 64]
    int n_nodes)
{
    __shared__ float sWT[D * D];          // 16 KB, staged once per block
    __shared__ float s_feat[8][D];        // per-warp feature row

    const int lane = threadIdx.x & 31;
    const int wim  = threadIdx.x >> 5;    // warp in block (0..7)
    const int gw   = (blockIdx.x * blockDim.x + threadIdx.x) >> 5;
    const int nwarps = (gridDim.x * blockDim.x) >> 5;
    const int c2 = lane * 2;              // channel pair (c2, c2+1)

    // stage WT once (float4, coalesced, conflict-free)
    {
        const float4* src4 = (const float4*)g_WT;
        float4* dst4 = (float4*)sWT;
        for (int i = threadIdx.x; i < (D * D) / 4; i += 256)
            dst4[i] = src4[i];
    }
    __syncthreads();

    const float sc = scale[0];
    const float2 bv = *(const float2*)(bvec + c2);

    for (int node = gw; node < n_nodes; node += nwarps) {
        const int s     = g_off[node];
        const int e_end = g_off[node + 1];

        // Plain sums: softmax max-shift is invariant in agg = sum(m*e)/sum(e),
        // and m <= ~10 so exp(m) cannot overflow fp32.
        float2 se  = make_float2(0.f, 0.f);
        float2 sme = make_float2(0.f, 0.f);
        #pragma unroll 4
        for (int e = s; e < e_end; ++e) {
            const int sp = __ldg(&src[e]);
            const float2 a = *(const float2*)(nf + sp * D + c2);
            const float2 b = *(const float2*)(ef + (size_t)e * D + c2);
            const float mxv = fmaxf(a.x + b.x, 0.f) + EPS_M;
            const float myv = fmaxf(a.y + b.y, 0.f) + EPS_M;
            const float px = __expf(mxv);
            const float py = __expf(myv);
            se.x += px;                 se.y += py;
            sme.x = fmaf(mxv, px, sme.x); sme.y = fmaf(myv, py, sme.y);
        }
        float2 agg;
        agg.x = (se.x > 0.f) ? (sme.x / se.x) : 0.f;
        agg.y = (se.y > 0.f) ? (sme.y / se.y) : 0.f;

        const float2 h = *(const float2*)(nf + (size_t)node * D + c2);

        // warp reductions: ||agg||^2, ||h||^2
        float a2 = fmaf(agg.x, agg.x, agg.y * agg.y);
        float h2 = fmaf(h.x, h.x, h.y * h.y);
        #pragma unroll
        for (int o = 16; o > 0; o >>= 1) {
            a2 += __shfl_xor_sync(0xffffffffu, a2, o);
            h2 += __shfl_xor_sync(0xffffffffu, h2, o);
        }

        // MessageNorm + residual
        const float coef = (sqrtf(h2) * sc) / fmaxf(sqrtf(a2), 1e-12f);
        float2 feat;
        feat.x = fmaf(agg.x, coef, h.x);
        feat.y = fmaf(agg.y, coef, h.y);

        *(float2*)(s_feat[wim] + c2) = feat;
        __syncwarp();

        // fused linear: out[node][c] = b[c] + sum_d feat[d] * WT[d][c]
        float2 acc = bv;
        const float* __restrict__ sf = s_feat[wim];
        #pragma unroll
        for (int d = 0; d < D; ++d) {
            const float f = sf[d];                              // broadcast
            const float2 w2 = *(const float2*)(sWT + d * D + c2); // conflict-free
            acc.x = fmaf(f, w2.x, acc.x);
            acc.y = fmaf(f, w2.y, acc.y);
        }
        *(float2*)(out + (size_t)node * D + c2) = acc;
        __syncwarp();   // protect s_feat WAR for next node iteration
    }
}

extern "C" void kernel_launch(void* const* d_in, const int* in_sizes, int n_in,
                              void* d_out, int out_size)
{
    const float* nf    = (const float*)d_in[0];
    const float* ef    = (const float*)d_in[1];
    const float* W     = (const float*)d_in[2];
    const float* bvec  = (const float*)d_in[3];
    const float* scale = (const float*)d_in[4];
    const int*   src   = (const int*)d_in[5];
    const int*   dst   = (const int*)d_in[6];
    float* out = (float*)d_out;

    const int n_nodes = in_sizes[0] / D;
    const int n_edges = in_sizes[5];

    prep_kernel<<<(n_nodes + 256) / 256, 256>>>(dst, W, n_nodes, n_edges);
    genconv_kernel<<<1216, 256>>>(nf, ef, bvec, scale, src, out, n_nodes);
}

// round 4
// speedup vs baseline: 13.0625x; 1.0311x over previous
#include <cuda_runtime.h>
#include <math.h>

#define D 64
#define EPS_M 1e-7f
#define N_MAX 100001
#define NB 4            // nodes per warp-chunk (register-tiled GEMM)

__device__ float g_WT[D * D];       // g_WT[d*64 + c] = W[c][d]
__device__ int   g_off[N_MAX + 1];  // CSR offsets into sorted dst

// ---- single pre-kernel: CSR offsets + W transpose ----
__global__ void prep_kernel(const int* __restrict__ dst,
                            const float* __restrict__ W,
                            int n_nodes, int n_edges)
{
    const int i = blockIdx.x * blockDim.x + threadIdx.x;
    if (i < D * D) {
        int r = i >> 6, c = i & 63;       // W[r][c]
        g_WT[c * D + r] = W[i];
    }
    if (i <= n_nodes) {
        if (i == n_nodes) { g_off[i] = n_edges; }
        else {
            int lo = 0, hi = n_edges;
            while (lo < hi) { int mid = (lo + hi) >> 1; if (dst[mid] < i) lo = mid + 1; else hi = mid; }
            g_off[i] = lo;
        }
    }
}

// ---- main kernel: warp handles NB consecutive nodes, then 4x64 mini-GEMM ----
__global__ void __launch_bounds__(256) genconv_kernel(
    const float* __restrict__ nf,     // [N, 64]
    const float* __restrict__ ef,     // [E, 64]
    const float* __restrict__ bvec,   // [64]
    const float* __restrict__ scale,  // [1]
    const int*   __restrict__ src,    // [E]
    float*       __restrict__ out,    // [N, 64]
    int n_nodes)
{
    __shared__ float sWT[D * D];          // 16 KB
    __shared__ float s_feat[8][NB][D];    // 8 KB

    const int lane = threadIdx.x & 31;
    const int wim  = threadIdx.x >> 5;
    const int q    = lane & 15;           // channel-quad index (0..15)
    const int eo   = lane >> 4;           // edge offset (0/1): half-warp per edge
    const int c4   = q * 4;               // channels c4..c4+3 in edge loop
    const int c2   = lane * 2;            // channels c2,c2+1 in GEMM
    const int gw   = (blockIdx.x * blockDim.x + threadIdx.x) >> 5;
    const int nwarps = (gridDim.x * blockDim.x) >> 5;

    {   // stage WT once per block
        const float4* s4 = (const float4*)g_WT;
        float4* d4 = (float4*)sWT;
        for (int i = threadIdx.x; i < (D * D) / 4; i += 256) d4[i] = s4[i];
    }
    __syncthreads();

    const float sc = scale[0];
    const float2 bv = *(const float2*)(bvec + c2);
    const int nchunks = (n_nodes + NB - 1) / NB;

    for (int chunk = gw; chunk < nchunks; chunk += nwarps) {
        const int base = chunk * NB;

        #pragma unroll
        for (int i = 0; i < NB; ++i) {
            const int node = base + i;
            float4 se  = make_float4(0.f, 0.f, 0.f, 0.f);
            float4 sme = make_float4(0.f, 0.f, 0.f, 0.f);
            float4 h4  = make_float4(0.f, 0.f, 0.f, 0.f);

            if (node < n_nodes) {
                h4 = *(const float4*)(nf + node * D + c4);
                const int s    = g_off[node];
                const int eend = g_off[node + 1];
                // two edges per iteration: half-warp eo handles edge e+eo
                #pragma unroll 2
                for (int e = s + eo; e < eend; e += 2) {
                    const int sp = __ldg(&src[e]);
                    const float4 a = *(const float4*)(nf + sp * D + c4);
                    const float4 b = *(const float4*)(ef + (size_t)e * D + c4);
                    const float m0 = fmaxf(a.x + b.x, 0.f) + EPS_M;
                    const float m1 = fmaxf(a.y + b.y, 0.f) + EPS_M;
                    const float m2 = fmaxf(a.z + b.z, 0.f) + EPS_M;
                    const float m3 = fmaxf(a.w + b.w, 0.f) + EPS_M;
                    const float p0 = __expf(m0), p1 = __expf(m1);
                    const float p2 = __expf(m2), p3 = __expf(m3);
                    se.x += p0; se.y += p1; se.z += p2; se.w += p3;
                    sme.x = fmaf(m0, p0, sme.x); sme.y = fmaf(m1, p1, sme.y);
                    sme.z = fmaf(m2, p2, sme.z); sme.w = fmaf(m3, p3, sme.w);
                }
            }
            // combine the two edge-halves (lane q <-> lane q+16)
            se.x += __shfl_xor_sync(0xffffffffu, se.x, 16);
            se.y += __shfl_xor_sync(0xffffffffu, se.y, 16);
            se.z += __shfl_xor_sync(0xffffffffu, se.z, 16);
            se.w += __shfl_xor_sync(0xffffffffu, se.w, 16);
            sme.x += __shfl_xor_sync(0xffffffffu, sme.x, 16);
            sme.y += __shfl_xor_sync(0xffffffffu, sme.y, 16);
            sme.z += __shfl_xor_sync(0xffffffffu, sme.z, 16);
            sme.w += __shfl_xor_sync(0xffffffffu, sme.w, 16);

            float4 agg;
            agg.x = (se.x > 0.f) ? (sme.x / se.x) : 0.f;
            agg.y = (se.y > 0.f) ? (sme.y / se.y) : 0.f;
            agg.z = (se.z > 0.f) ? (sme.z / se.z) : 0.f;
            agg.w = (se.w > 0.f) ? (sme.w / se.w) : 0.f;

            // norms over 64 channels (each 16-lane group holds the full set)
            float a2 = fmaf(agg.x, agg.x, fmaf(agg.y, agg.y, fmaf(agg.z, agg.z, agg.w * agg.w)));
            float h2 = fmaf(h4.x, h4.x, fmaf(h4.y, h4.y, fmaf(h4.z, h4.z, h4.w * h4.w)));
            #pragma unroll
            for (int o = 8; o > 0; o >>= 1) {
                a2 += __shfl_xor_sync(0xffffffffu, a2, o);
                h2 += __shfl_xor_sync(0xffffffffu, h2, o);
            }

            const float coef = (sqrtf(h2) * sc) / fmaxf(sqrtf(a2), 1e-12f);
            if (lane < 16) {
                float4 f;
                f.x = fmaf(agg.x, coef, h4.x);
                f.y = fmaf(agg.y, coef, h4.y);
                f.z = fmaf(agg.z, coef, h4.z);
                f.w = fmaf(agg.w, coef, h4.w);
                *(float4*)&s_feat[wim][i][c4] = f;
            }
        }
        __syncwarp();

        // mini-GEMM: out[base..base+3][c2,c2+1] = b + feat @ WT
        float2 acc[NB];
        #pragma unroll
        for (int i = 0; i < NB; ++i) acc[i] = bv;

        #pragma unroll
        for (int d4 = 0; d4 < D; d4 += 4) {
            const float2 w0 = *(const float2*)(sWT + (d4 + 0) * D + c2);
            const float2 w1 = *(const float2*)(sWT + (d4 + 1) * D + c2);
            const float2 w2 = *(const float2*)(sWT + (d4 + 2) * D + c2);
            const float2 w3 = *(const float2*)(sWT + (d4 + 3) * D + c2);
            #pragma unroll
            for (int i = 0; i < NB; ++i) {
                const float4 f = *(const float4*)&s_feat[wim][i][d4];  // broadcast
                acc[i].x = fmaf(f.x, w0.x, acc[i].x); acc[i].y = fmaf(f.x, w0.y, acc[i].y);
                acc[i].x = fmaf(f.y, w1.x, acc[i].x); acc[i].y = fmaf(f.y, w1.y, acc[i].y);
                acc[i].x = fmaf(f.z, w2.x, acc[i].x); acc[i].y = fmaf(f.z, w2.y, acc[i].y);
                acc[i].x = fmaf(f.w, w3.x, acc[i].x); acc[i].y = fmaf(f.w, w3.y, acc[i].y);
            }
        }
        #pragma unroll
        for (int i = 0; i < NB; ++i)
            if (base + i < n_nodes)
                *(float2*)(out + (size_t)(base + i) * D + c2) = acc[i];
        __syncwarp();   // protect s_feat WAR for next chunk
    }
}

extern "C" void kernel_launch(void* const* d_in, const int* in_sizes, int n_in,
                              void* d_out, int out_size)
{
    const float* nf    = (const float*)d_in[0];
    const float* ef    = (const float*)d_in[1];
    const float* W     = (const float*)d_in[2];
    const float* bvec  = (const float*)d_in[3];
    const float* scale = (const float*)d_in[4];
    const int*   src   = (const int*)d_in[5];
    const int*   dst   = (const int*)d_in[6];
    float* out = (float*)d_out;

    const int n_nodes = in_sizes[0] / D;
    const int n_edges = in_sizes[5];

    prep_kernel<<<(n_nodes + 256) / 256, 256>>>(dst, W, n_nodes, n_edges);
    genconv_kernel<<<1480, 256>>>(nf, ef, bvec, scale, src, out, n_nodes);
}

// round 5
// speedup vs baseline: 14.5918x; 1.1171x over previous
#include <cuda_runtime.h>
#include <math.h>

#define D 64
#define EPS_M 1e-7f
#define N_MAX 100001
#define NB 4            // nodes per warp-chunk (register-tiled GEMM)

__device__ float g_WT[D * D];       // g_WT[d*64 + c] = W[c][d]
__device__ int   g_off[N_MAX + 1];  // CSR offsets into sorted dst

// ---- single pre-kernel: CSR offsets + W transpose ----
__global__ void prep_kernel(const int* __restrict__ dst,
                            const float* __restrict__ W,
                            int n_nodes, int n_edges)
{
    const int i = blockIdx.x * blockDim.x + threadIdx.x;
    if (i < D * D) {
        int r = i >> 6, c = i & 63;       // W[r][c]
        g_WT[c * D + r] = W[i];
    }
    if (i <= n_nodes) {
        if (i == n_nodes) { g_off[i] = n_edges; }
        else {
            int lo = 0, hi = n_edges;
            while (lo < hi) { int mid = (lo + hi) >> 1; if (dst[mid] < i) lo = mid + 1; else hi = mid; }
            g_off[i] = lo;
        }
    }
}

__device__ __forceinline__ void edge_step(const float4 a, const float4 b,
                                          float4& se, float4& sme)
{
    const float m0 = fmaxf(a.x + b.x, 0.f) + EPS_M;
    const float m1 = fmaxf(a.y + b.y, 0.f) + EPS_M;
    const float m2 = fmaxf(a.z + b.z, 0.f) + EPS_M;
    const float m3 = fmaxf(a.w + b.w, 0.f) + EPS_M;
    const float p0 = __expf(m0), p1 = __expf(m1);
    const float p2 = __expf(m2), p3 = __expf(m3);
    se.x += p0; se.y += p1; se.z += p2; se.w += p3;
    sme.x = fmaf(m0, p0, sme.x); sme.y = fmaf(m1, p1, sme.y);
    sme.z = fmaf(m2, p2, sme.z); sme.w = fmaf(m3, p3, sme.w);
}

// ---- main kernel: warp handles NB consecutive nodes, then 4x64 mini-GEMM ----
__global__ void __launch_bounds__(256) genconv_kernel(
    const float* __restrict__ nf,     // [N, 64]
    const float* __restrict__ ef,     // [E, 64]
    const float* __restrict__ bvec,   // [64]
    const float* __restrict__ scale,  // [1]
    const int*   __restrict__ src,    // [E]
    float*       __restrict__ out,    // [N, 64]
    int n_nodes)
{
    __shared__ float sWT[D * D];          // 16 KB
    __shared__ float s_feat[8][NB][D];    // 8 KB

    const int lane = threadIdx.x & 31;
    const int wim  = threadIdx.x >> 5;
    const int q    = lane & 15;           // channel-quad index (0..15)
    const int eo   = lane >> 4;           // edge offset (0/1): half-warp per edge
    const int c4   = q * 4;               // channels c4..c4+3 in edge loop
    const int c2   = lane * 2;            // channels c2,c2+1 in GEMM
    const int gw   = (blockIdx.x * blockDim.x + threadIdx.x) >> 5;
    const int nwarps = (gridDim.x * blockDim.x) >> 5;

    {   // stage WT once per block
        const float4* s4 = (const float4*)g_WT;
        float4* d4 = (float4*)sWT;
        for (int i = threadIdx.x; i < (D * D) / 4; i += 256) d4[i] = s4[i];
    }
    __syncthreads();

    const float sc = scale[0];
    const float2 bv = *(const float2*)(bvec + c2);
    const int nchunks = (n_nodes + NB - 1) / NB;

    for (int chunk = gw; chunk < nchunks; chunk += nwarps) {
        const int base = chunk * NB;

        #pragma unroll
        for (int i = 0; i < NB; ++i) {
            const int node = base + i;
            float4 se  = make_float4(0.f, 0.f, 0.f, 0.f);
            float4 sme = make_float4(0.f, 0.f, 0.f, 0.f);
            float4 h4  = make_float4(0.f, 0.f, 0.f, 0.f);

            if (node < n_nodes) {
                h4 = *(const float4*)(nf + node * D + c4);
                const int s    = g_off[node];
                const int eend = g_off[node + 1];
                int e = s + eo;
                // pipelined: 2 edges per half-warp per iter = 4 edges/warp in flight
                for (; e + 2 < eend; e += 4) {
                    const int sp0 = __ldg(&src[e]);
                    const int sp1 = __ldg(&src[e + 2]);
                    const float4 b0 = __ldcs((const float4*)(ef + (size_t)e * D + c4));
                    const float4 b1 = __ldcs((const float4*)(ef + (size_t)(e + 2) * D + c4));
                    const float4 a0 = *(const float4*)(nf + sp0 * D + c4);
                    const float4 a1 = *(const float4*)(nf + sp1 * D + c4);
                    edge_step(a0, b0, se, sme);
                    edge_step(a1, b1, se, sme);
                }
                if (e < eend) {
                    const int sp0 = __ldg(&src[e]);
                    const float4 b0 = __ldcs((const float4*)(ef + (size_t)e * D + c4));
                    const float4 a0 = *(const float4*)(nf + sp0 * D + c4);
                    edge_step(a0, b0, se, sme);
                }
            }
            // combine the two edge-halves (lane q <-> lane q+16)
            se.x += __shfl_xor_sync(0xffffffffu, se.x, 16);
            se.y += __shfl_xor_sync(0xffffffffu, se.y, 16);
            se.z += __shfl_xor_sync(0xffffffffu, se.z, 16);
            se.w += __shfl_xor_sync(0xffffffffu, se.w, 16);
            sme.x += __shfl_xor_sync(0xffffffffu, sme.x, 16);
            sme.y += __shfl_xor_sync(0xffffffffu, sme.y, 16);
            sme.z += __shfl_xor_sync(0xffffffffu, sme.z, 16);
            sme.w += __shfl_xor_sync(0xffffffffu, sme.w, 16);

            float4 agg;
            agg.x = (se.x > 0.f) ? (sme.x / se.x) : 0.f;
            agg.y = (se.y > 0.f) ? (sme.y / se.y) : 0.f;
            agg.z = (se.z > 0.f) ? (sme.z / se.z) : 0.f;
            agg.w = (se.w > 0.f) ? (sme.w / se.w) : 0.f;

            float a2 = fmaf(agg.x, agg.x, fmaf(agg.y, agg.y, fmaf(agg.z, agg.z, agg.w * agg.w)));
            float h2 = fmaf(h4.x, h4.x, fmaf(h4.y, h4.y, fmaf(h4.z, h4.z, h4.w * h4.w)));
            #pragma unroll
            for (int o = 8; o > 0; o >>= 1) {
                a2 += __shfl_xor_sync(0xffffffffu, a2, o);
                h2 += __shfl_xor_sync(0xffffffffu, h2, o);
            }

            const float coef = (sqrtf(h2) * sc) / fmaxf(sqrtf(a2), 1e-12f);
            if (lane < 16) {
                float4 f;
                f.x = fmaf(agg.x, coef, h4.x);
                f.y = fmaf(agg.y, coef, h4.y);
                f.z = fmaf(agg.z, coef, h4.z);
                f.w = fmaf(agg.w, coef, h4.w);
                *(float4*)&s_feat[wim][i][c4] = f;
            }
        }
        __syncwarp();

        // mini-GEMM: out[base..base+3][c2,c2+1] = b + feat @ WT
        float2 acc[NB];
        #pragma unroll
        for (int i = 0; i < NB; ++i) acc[i] = bv;

        #pragma unroll
        for (int d4 = 0; d4 < D; d4 += 4) {
            const float2 w0 = *(const float2*)(sWT + (d4 + 0) * D + c2);
            const float2 w1 = *(const float2*)(sWT + (d4 + 1) * D + c2);
            const float2 w2 = *(const float2*)(sWT + (d4 + 2) * D + c2);
            const float2 w3 = *(const float2*)(sWT + (d4 + 3) * D + c2);
            #pragma unroll
            for (int i = 0; i < NB; ++i) {
                const float4 f = *(const float4*)&s_feat[wim][i][d4];  // broadcast
                acc[i].x = fmaf(f.x, w0.x, acc[i].x); acc[i].y = fmaf(f.x, w0.y, acc[i].y);
                acc[i].x = fmaf(f.y, w1.x, acc[i].x); acc[i].y = fmaf(f.y, w1.y, acc[i].y);
                acc[i].x = fmaf(f.z, w2.x, acc[i].x); acc[i].y = fmaf(f.z, w2.y, acc[i].y);
                acc[i].x = fmaf(f.w, w3.x, acc[i].x); acc[i].y = fmaf(f.w, w3.y, acc[i].y);
            }
        }
        #pragma unroll
        for (int i = 0; i < NB; ++i)
            if (base + i < n_nodes)
                *(float2*)(out + (size_t)(base + i) * D + c2) = acc[i];
        __syncwarp();   // protect s_feat WAR for next chunk
    }
}

extern "C" void kernel_launch(void* const* d_in, const int* in_sizes, int n_in,
                              void* d_out, int out_size)
{
    const float* nf    = (const float*)d_in[0];
    const float* ef    = (const float*)d_in[1];
    const float* W     = (const float*)d_in[2];
    const float* bvec  = (const float*)d_in[3];
    const float* scale = (const float*)d_in[4];
    const int*   src   = (const int*)d_in[5];
    const int*   dst   = (const int*)d_in[6];
    float* out = (float*)d_out;

    const int n_nodes = in_sizes[0] / D;
    const int n_edges = in_sizes[5];

    prep_kernel<<<(n_nodes + 256) / 256, 256>>>(dst, W, n_nodes, n_edges);
    genconv_kernel<<<1480, 256>>>(nf, ef, bvec, scale, src, out, n_nodes);
}